// round 9
// baseline (speedup 1.0000x reference)
#include <cuda_runtime.h>
#include <cuda_bf16.h>
#include <cstdint>

// Problem constants
#define BDIM 1024
#define DIN  64
#define DHID 128
#define BN_EPS 1e-5f

typedef unsigned long long u64;

// Scratch (device globals; no allocations allowed)
__device__ float g_At[DHID * BDIM];   // A^T: [k][i]
__device__ float g_Ct[DHID * BDIM];   // C^T: [k][j]
__device__ float g_s[DHID];           // folded scale  gamma*rsigma*W2
__device__ float g_tpart[DHID];       // per-channel bias contribution
__device__ float g_t[1];              // folded bias
__device__ float g_P[BDIM];           // 0.5 * sum_k s_k * At[k][i]
__device__ float g_R[BDIM];           // 0.5 * sum_k s_k * Ct[k][j]

// ---------------------------------------------------------------------------
// Kernel 1: A^T / C^T precompute.  grid=256 blocks (4 rows each), 128 threads.
// (verbatim from the passing R1/R2 kernel)
// ---------------------------------------------------------------------------
__global__ __launch_bounds__(128) void prep_kernel(
    const float* __restrict__ x, const float* __restrict__ W1,
    const float* __restrict__ b1)
{
    __shared__ float xs[4][DIN];
    const int i0 = blockIdx.x * 4;
    const int tid = threadIdx.x;
    for (int e = tid; e < 4 * DIN; e += 128)
        xs[e >> 6][e & 63] = x[i0 * DIN + e];
    __syncthreads();

    const int k = tid;
    float accA[4], accC[4];
#pragma unroll
    for (int r = 0; r < 4; r++) { accA[r] = b1[k]; accC[r] = 0.f; }
#pragma unroll 8
    for (int d = 0; d < DIN; d++) {
        const float w1 = W1[d * DHID + k];
        const float w2 = W1[(d + DIN) * DHID + k];
#pragma unroll
        for (int r = 0; r < 4; r++) {
            const float xv = xs[r][d];
            accA[r] = fmaf(xv, w1, accA[r]);
            accC[r] = fmaf(xv, w2, accC[r]);
        }
    }
#pragma unroll
    for (int r = 0; r < 4; r++) {
        g_At[k * BDIM + i0 + r] = accA[r];
        g_Ct[k * BDIM + i0 + r] = accC[r];
    }
}

// ---------------------------------------------------------------------------
// Kernel 2: per-channel stats WITHOUT a global sort.
// 128 blocks x 256 threads.  Each warp sorts an independent 128-element chunk
// of the channel's c row entirely in registers (strides 1-2 local, 4-64 shfl;
// 28 stages, zero block barriers), computes warp-local suffix sums of c, c^2,
// and writes (sorted, suf1, suf2) to smem.  One __syncthreads, then each
// thread answers its 4 queries against all 8 chunks (independent searches,
// good MLP) and the block reduces S/Q -> BN fold.
// ---------------------------------------------------------------------------
__global__ __launch_bounds__(256) void sortstats_kernel(
    const float* __restrict__ gamma, const float* __restrict__ beta,
    const float* __restrict__ W2)
{
    __shared__ float sc[8 * 132];     // per-chunk sorted values (+INF sentinel @128)
    __shared__ float ssf[8 * 132];    // per-chunk suffix sums of c     (0 @128)
    __shared__ float ssf2[8 * 132];   // per-chunk suffix sums of c^2   (0 @128)
    __shared__ float wr1[8];
    __shared__ float wr2[8];

    const int k = blockIdx.x;
    const int tid = threadIdx.x;
    const int lane = tid & 31;
    const int warp = tid >> 5;

    // load this warp's 128-element chunk: element le = lane*4 + r
    const float4 cv = *(const float4*)&g_Ct[k * BDIM + tid * 4];
    float v[4] = {cv.x, cv.y, cv.z, cv.w};

    // --- warp-local bitonic sort ascending over le in [0,128) ---
    for (int size = 2; size <= 128; size <<= 1) {
        for (int stride = size >> 1; stride > 0; stride >>= 1) {
            float pv[4];
            if (stride >= 4) {
#pragma unroll
                for (int r = 0; r < 4; r++)
                    pv[r] = __shfl_xor_sync(0xffffffffu, v[r], stride >> 2);
            } else {
#pragma unroll
                for (int r = 0; r < 4; r++) pv[r] = v[r ^ stride];
            }
#pragma unroll
            for (int r = 0; r < 4; r++) {
                const int le = lane * 4 + r;
                const bool up = ((le & size) == 0);
                const bool lower = ((le & stride) == 0);
                const float mn = fminf(v[r], pv[r]);
                const float mx = fmaxf(v[r], pv[r]);
                v[r] = (up == lower) ? mn : mx;
            }
        }
    }

    // --- warp-local suffix sums of v and v^2 ---
    float ls1[4], ls2[4];
    ls1[3] = v[3];               ls2[3] = v[3] * v[3];
    ls1[2] = ls1[3] + v[2];      ls2[2] = fmaf(v[2], v[2], ls2[3]);
    ls1[1] = ls1[2] + v[1];      ls2[1] = fmaf(v[1], v[1], ls2[2]);
    ls1[0] = ls1[1] + v[0];      ls2[0] = fmaf(v[0], v[0], ls2[1]);

    float w1 = ls1[0], w2 = ls2[0];   // inclusive suffix over lanes of this warp
#pragma unroll
    for (int o = 1; o < 32; o <<= 1) {
        const float t1 = __shfl_down_sync(0xffffffffu, w1, o);
        const float t2 = __shfl_down_sync(0xffffffffu, w2, o);
        if (lane + o < 32) { w1 += t1; w2 += t2; }
    }
    const float base1 = w1 - ls1[0];  // suffix over later lanes only
    const float base2 = w2 - ls2[0];

    const int cb = warp * 132;
#pragma unroll
    for (int r = 0; r < 4; r++) {
        const int le = lane * 4 + r;
        sc[cb + le]   = v[r];
        ssf[cb + le]  = ls1[r] + base1;
        ssf2[cb + le] = ls2[r] + base2;
    }
    if (lane == 0) {
        sc[cb + 128]   = __int_as_float(0x7f800000);   // +INF sentinel
        ssf[cb + 128]  = 0.f;
        ssf2[cb + 128] = 0.f;
    }
    __syncthreads();

    // --- queries: 4 per thread, each against all 8 chunks ---
    const float4 av4 = *(const float4*)&g_At[k * BDIM + tid * 4];
    const float av[4] = {av4.x, av4.y, av4.z, av4.w};
    float S = 0.f, Q = 0.f;
#pragma unroll
    for (int r = 0; r < 4; r++) {
        const float a = av[r];
        const float th = -a;
        float ntot = 0.f, s1t = 0.f, s2t = 0.f;
#pragma unroll
        for (int m = 0; m < 8; m++) {
            const int base = m * 132;
            int lo = 0, hi = 128;
#pragma unroll
            for (int it = 0; it < 8; it++) {     // 8 iters: guaranteed lo==hi
                const int mid = (lo + hi) >> 1;
                if (sc[base + mid] > th) hi = mid; else lo = mid + 1;
            }
            ntot += (float)(128 - lo);
            s1t  += ssf[base + lo];
            s2t  += ssf2[base + lo];
        }
        S += fmaf(ntot, a, s1t);
        Q += fmaf(ntot * a, a, fmaf(2.f * a, s1t, s2t));
    }

    // --- block reduce S, Q and BN fold ---
#pragma unroll
    for (int o = 16; o > 0; o >>= 1) {
        S += __shfl_xor_sync(0xffffffffu, S, o);
        Q += __shfl_xor_sync(0xffffffffu, Q, o);
    }
    if (lane == 0) { wr1[warp] = S; wr2[warp] = Q; }
    __syncthreads();
    if (tid == 0) {
        float St = 0.f, Qt = 0.f;
#pragma unroll
        for (int w = 0; w < 8; w++) { St += wr1[w]; Qt += wr2[w]; }
        const float N = (float)BDIM * (float)BDIM;
        const float mean = St / N;
        const float var  = Qt / N - mean * mean;
        const float rs   = rsqrtf(var + BN_EPS);
        const float wk   = W2[k];
        g_s[k] = gamma[k] * rs * wk;
        g_tpart[k] = (beta[k] - mean * rs * gamma[k]) * wk;
    }
}

// ---------------------------------------------------------------------------
// Kernel 3: block 0 reduces t; blocks 1..8 compute P chunks; 9..16 R chunks.
// (verbatim from the passing R2 kernel)
// ---------------------------------------------------------------------------
__global__ __launch_bounds__(128) void finalize_pr_kernel(const float* __restrict__ b2)
{
    const int b = blockIdx.x;
    const int tid = threadIdx.x;
    if (b == 0) {
        __shared__ float red[128];
        red[tid] = g_tpart[tid];
        __syncthreads();
        for (int s = 64; s > 0; s >>= 1) {
            if (tid < s) red[tid] += red[tid + s];
            __syncthreads();
        }
        if (tid == 0) g_t[0] = red[0] + b2[0];
    } else {
        __shared__ float ss[DHID];
        ss[tid] = g_s[tid];
        __syncthreads();
        const bool isP = (b <= 8);
        const int idx = ((b - 1) & 7) * 128 + tid;
        const float* src = isP ? g_At : g_Ct;
        float acc = 0.f;
#pragma unroll 16
        for (int k = 0; k < DHID; k++)
            acc = fmaf(ss[k], src[k * BDIM + idx], acc);
        if (isP) g_P[idx] = 0.5f * acc;
        else     g_R[idx] = 0.5f * acc;
    }
}

// ---------------------------------------------------------------------------
// Kernel 4 (dominant): out[i][j] = t + P_i + R_j + sum_k (s_k/2)|At[k][i]+Ct[k][j]|
// (verbatim from the R2 kernel: 64x64 tile, 256 threads, 4i x 4j, j-packed)
// ---------------------------------------------------------------------------
__global__ __launch_bounds__(256) void pass2_kernel(float* __restrict__ out)
{
    __shared__ float As[64][64];   // [kk][i]
    __shared__ float Cs[64][64];   // [kk][j]
    __shared__ u64 s2h[DHID];      // (s/2, s/2) packed
    __shared__ float Ps[64];
    __shared__ float Rs[64];

    const int i0 = blockIdx.y * 64;
    const int j0 = blockIdx.x * 64;
    const int tid = threadIdx.x;

    if (tid < DHID) {
        u64 p;
        asm("mov.b64 %0, {%1, %1};" : "=l"(p) : "f"(0.5f * g_s[tid]));
        s2h[tid] = p;
    }
    if (tid < 64) Ps[tid] = g_P[i0 + tid];
    else if (tid < 128) Rs[tid - 64] = g_R[j0 + tid - 64];

    const int ty = tid >> 4;   // 0..15 -> i sub-tile of 4
    const int tx = tid & 15;   // 0..15 -> j sub-tile of 4

    u64 acc2[4][2];   // [i][jpair]
#pragma unroll
    for (int q = 0; q < 4; q++) { acc2[q][0] = 0ull; acc2[q][1] = 0ull; }
    const u64 MASK = 0x7FFFFFFF7FFFFFFFull;

    for (int kc = 0; kc < 2; kc++) {
        __syncthreads();
        for (int e = tid; e < 64 * 16; e += 256) {
            const int kk = e >> 4, vv = e & 15;
            const int kg = kc * 64 + kk;
            *(float4*)&As[kk][vv * 4] = *(const float4*)&g_At[kg * BDIM + i0 + vv * 4];
            *(float4*)&Cs[kk][vv * 4] = *(const float4*)&g_Ct[kg * BDIM + j0 + vv * 4];
        }
        __syncthreads();

#pragma unroll 8
        for (int kk = 0; kk < 64; kk++) {
            const float4 a4 = *(const float4*)&As[kk][ty * 4];
            const ulonglong2 cp = *(const ulonglong2*)&Cs[kk][tx * 4];
            const u64 sk = s2h[kc * 64 + kk];
            u64 av[4];
            asm("mov.b64 %0, {%1, %1};" : "=l"(av[0]) : "f"(a4.x));
            asm("mov.b64 %0, {%1, %1};" : "=l"(av[1]) : "f"(a4.y));
            asm("mov.b64 %0, {%1, %1};" : "=l"(av[2]) : "f"(a4.z));
            asm("mov.b64 %0, {%1, %1};" : "=l"(av[3]) : "f"(a4.w));
            const u64 cj[2] = {cp.x, cp.y};
#pragma unroll
            for (int q = 0; q < 4; q++) {
#pragma unroll
                for (int r = 0; r < 2; r++) {
                    u64 vs;
                    asm("add.rn.f32x2 %0, %1, %2;" : "=l"(vs) : "l"(av[q]), "l"(cj[r]));
                    vs &= MASK;   // |.| on both packed lanes
                    asm("fma.rn.f32x2 %0, %1, %2, %3;"
                        : "=l"(acc2[q][r]) : "l"(vs), "l"(sk), "l"(acc2[q][r]));
                }
            }
        }
    }

    const float t = g_t[0];
    const float r0 = Rs[tx * 4 + 0];
    const float r1 = Rs[tx * 4 + 1];
    const float r2 = Rs[tx * 4 + 2];
    const float r3 = Rs[tx * 4 + 3];
#pragma unroll
    for (int q = 0; q < 4; q++) {
        float v0, v1, v2, v3;
        asm("mov.b64 {%0, %1}, %2;" : "=f"(v0), "=f"(v1) : "l"(acc2[q][0]));
        asm("mov.b64 {%0, %1}, %2;" : "=f"(v2), "=f"(v3) : "l"(acc2[q][1]));
        const float base = t + Ps[ty * 4 + q];
        float4 o;
        o.x = v0 + base + r0;
        o.y = v1 + base + r1;
        o.z = v2 + base + r2;
        o.w = v3 + base + r3;
        *(float4*)&out[(size_t)(i0 + ty * 4 + q) * BDIM + j0 + tx * 4] = o;
    }
}

// ---------------------------------------------------------------------------
extern "C" void kernel_launch(void* const* d_in, const int* in_sizes, int n_in,
                              void* d_out, int out_size)
{
    const float* x     = (const float*)d_in[0];
    const float* W1    = (const float*)d_in[1];
    const float* b1    = (const float*)d_in[2];
    const float* gamma = (const float*)d_in[3];
    const float* beta  = (const float*)d_in[4];
    const float* W2    = (const float*)d_in[5];
    const float* b2    = (const float*)d_in[6];
    float* out = (float*)d_out;

    prep_kernel<<<BDIM / 4, 128>>>(x, W1, b1);
    sortstats_kernel<<<DHID, 256>>>(gamma, beta, W2);
    finalize_pr_kernel<<<17, 128>>>(b2);
    pass2_kernel<<<dim3(16, 16), 256>>>(out);
}

// round 10
// speedup vs baseline: 1.4456x; 1.4456x over previous
#include <cuda_runtime.h>
#include <cuda_bf16.h>
#include <cstdint>

// Problem constants
#define BDIM 1024
#define DIN  64
#define DHID 128
#define BN_EPS 1e-5f

typedef unsigned long long u64;

// Scratch (device globals; no allocations allowed)
__device__ float g_At[DHID * BDIM];   // A^T: [k][i]
__device__ float g_Ct[DHID * BDIM];   // C^T: [k][j]
__device__ float g_s[DHID];           // folded scale  gamma*rsigma*W2
__device__ float g_tpart[DHID];       // per-channel bias contribution
__device__ float g_t[1];              // folded bias
__device__ float g_P[BDIM];           // 0.5 * sum_k s_k * At[k][i]
__device__ float g_R[BDIM];           // 0.5 * sum_k s_k * Ct[k][j]

// ---------------------------------------------------------------------------
// Kernel 1: A^T / C^T precompute.  grid=256 blocks (4 rows each), 128 threads.
// (verbatim R1)
// ---------------------------------------------------------------------------
__global__ __launch_bounds__(128) void prep_kernel(
    const float* __restrict__ x, const float* __restrict__ W1,
    const float* __restrict__ b1)
{
    __shared__ float xs[4][DIN];
    const int i0 = blockIdx.x * 4;
    const int tid = threadIdx.x;
    for (int e = tid; e < 4 * DIN; e += 128)
        xs[e >> 6][e & 63] = x[i0 * DIN + e];
    __syncthreads();

    const int k = tid;
    float accA[4], accC[4];
#pragma unroll
    for (int r = 0; r < 4; r++) { accA[r] = b1[k]; accC[r] = 0.f; }
#pragma unroll 8
    for (int d = 0; d < DIN; d++) {
        const float w1 = W1[d * DHID + k];
        const float w2 = W1[(d + DIN) * DHID + k];
#pragma unroll
        for (int r = 0; r < 4; r++) {
            const float xv = xs[r][d];
            accA[r] = fmaf(xv, w1, accA[r]);
            accC[r] = fmaf(xv, w2, accC[r]);
        }
    }
#pragma unroll
    for (int r = 0; r < 4; r++) {
        g_At[k * BDIM + i0 + r] = accA[r];
        g_Ct[k * BDIM + i0 + r] = accC[r];
    }
}

// ---------------------------------------------------------------------------
// Kernel 2: per-channel stats via 8 warp-local sorted chunks (verbatim R9).
// ---------------------------------------------------------------------------
__global__ __launch_bounds__(256) void sortstats_kernel(
    const float* __restrict__ gamma, const float* __restrict__ beta,
    const float* __restrict__ W2)
{
    __shared__ float sc[8 * 132];
    __shared__ float ssf[8 * 132];
    __shared__ float ssf2[8 * 132];
    __shared__ float wr1[8];
    __shared__ float wr2[8];

    const int k = blockIdx.x;
    const int tid = threadIdx.x;
    const int lane = tid & 31;
    const int warp = tid >> 5;

    const float4 cv = *(const float4*)&g_Ct[k * BDIM + tid * 4];
    float v[4] = {cv.x, cv.y, cv.z, cv.w};

    for (int size = 2; size <= 128; size <<= 1) {
        for (int stride = size >> 1; stride > 0; stride >>= 1) {
            float pv[4];
            if (stride >= 4) {
#pragma unroll
                for (int r = 0; r < 4; r++)
                    pv[r] = __shfl_xor_sync(0xffffffffu, v[r], stride >> 2);
            } else {
#pragma unroll
                for (int r = 0; r < 4; r++) pv[r] = v[r ^ stride];
            }
#pragma unroll
            for (int r = 0; r < 4; r++) {
                const int le = lane * 4 + r;
                const bool up = ((le & size) == 0);
                const bool lower = ((le & stride) == 0);
                const float mn = fminf(v[r], pv[r]);
                const float mx = fmaxf(v[r], pv[r]);
                v[r] = (up == lower) ? mn : mx;
            }
        }
    }

    float ls1[4], ls2[4];
    ls1[3] = v[3];               ls2[3] = v[3] * v[3];
    ls1[2] = ls1[3] + v[2];      ls2[2] = fmaf(v[2], v[2], ls2[3]);
    ls1[1] = ls1[2] + v[1];      ls2[1] = fmaf(v[1], v[1], ls2[2]);
    ls1[0] = ls1[1] + v[0];      ls2[0] = fmaf(v[0], v[0], ls2[1]);

    float w1 = ls1[0], w2 = ls2[0];
#pragma unroll
    for (int o = 1; o < 32; o <<= 1) {
        const float t1 = __shfl_down_sync(0xffffffffu, w1, o);
        const float t2 = __shfl_down_sync(0xffffffffu, w2, o);
        if (lane + o < 32) { w1 += t1; w2 += t2; }
    }
    const float base1 = w1 - ls1[0];
    const float base2 = w2 - ls2[0];

    const int cb = warp * 132;
#pragma unroll
    for (int r = 0; r < 4; r++) {
        const int le = lane * 4 + r;
        sc[cb + le]   = v[r];
        ssf[cb + le]  = ls1[r] + base1;
        ssf2[cb + le] = ls2[r] + base2;
    }
    if (lane == 0) {
        sc[cb + 128]   = __int_as_float(0x7f800000);
        ssf[cb + 128]  = 0.f;
        ssf2[cb + 128] = 0.f;
    }
    __syncthreads();

    const float4 av4 = *(const float4*)&g_At[k * BDIM + tid * 4];
    const float av[4] = {av4.x, av4.y, av4.z, av4.w};
    float S = 0.f, Q = 0.f;
#pragma unroll
    for (int r = 0; r < 4; r++) {
        const float a = av[r];
        const float th = -a;
        float ntot = 0.f, s1t = 0.f, s2t = 0.f;
#pragma unroll
        for (int m = 0; m < 8; m++) {
            const int base = m * 132;
            int lo = 0, hi = 128;
#pragma unroll
            for (int it = 0; it < 8; it++) {
                const int mid = (lo + hi) >> 1;
                if (sc[base + mid] > th) hi = mid; else lo = mid + 1;
            }
            ntot += (float)(128 - lo);
            s1t  += ssf[base + lo];
            s2t  += ssf2[base + lo];
        }
        S += fmaf(ntot, a, s1t);
        Q += fmaf(ntot * a, a, fmaf(2.f * a, s1t, s2t));
    }

#pragma unroll
    for (int o = 16; o > 0; o >>= 1) {
        S += __shfl_xor_sync(0xffffffffu, S, o);
        Q += __shfl_xor_sync(0xffffffffu, Q, o);
    }
    if (lane == 0) { wr1[warp] = S; wr2[warp] = Q; }
    __syncthreads();
    if (tid == 0) {
        float St = 0.f, Qt = 0.f;
#pragma unroll
        for (int w = 0; w < 8; w++) { St += wr1[w]; Qt += wr2[w]; }
        const float N = (float)BDIM * (float)BDIM;
        const float mean = St / N;
        const float var  = Qt / N - mean * mean;
        const float rs   = rsqrtf(var + BN_EPS);
        const float wk   = W2[k];
        g_s[k] = gamma[k] * rs * wk;
        g_tpart[k] = (beta[k] - mean * rs * gamma[k]) * wk;
    }
}

// ---------------------------------------------------------------------------
// Kernel 3: t / P / R  (verbatim R2)
// ---------------------------------------------------------------------------
__global__ __launch_bounds__(128) void finalize_pr_kernel(const float* __restrict__ b2)
{
    const int b = blockIdx.x;
    const int tid = threadIdx.x;
    if (b == 0) {
        __shared__ float red[128];
        red[tid] = g_tpart[tid];
        __syncthreads();
        for (int s = 64; s > 0; s >>= 1) {
            if (tid < s) red[tid] += red[tid + s];
            __syncthreads();
        }
        if (tid == 0) g_t[0] = red[0] + b2[0];
    } else {
        __shared__ float ss[DHID];
        ss[tid] = g_s[tid];
        __syncthreads();
        const bool isP = (b <= 8);
        const int idx = ((b - 1) & 7) * 128 + tid;
        const float* src = isP ? g_At : g_Ct;
        float acc = 0.f;
#pragma unroll 16
        for (int k = 0; k < DHID; k++)
            acc = fmaf(ss[k], src[k * BDIM + idx], acc);
        if (isP) g_P[idx] = 0.5f * acc;
        else     g_R[idx] = 0.5f * acc;
    }
}

// ---------------------------------------------------------------------------
// Kernel 4 (dominant): out[i][j] = t + P_i + R_j + sum_k (s_k/2)|At[k][i]+Ct[k][j]|
// 32x64 tile, 128 threads (4 warps), grid=(16,32)=512 blocks -> ~3.5 blocks/SM.
// Register tile 4i x 4j per thread (ty 0..7, tx 0..15); inner loop verbatim R2.
// ---------------------------------------------------------------------------
__global__ __launch_bounds__(128) void pass2_kernel(float* __restrict__ out)
{
    __shared__ float As[64][32];   // [kk][i]
    __shared__ float Cs[64][64];   // [kk][j]
    __shared__ u64 s2h[DHID];      // (s/2, s/2) packed
    __shared__ float Ps[32];
    __shared__ float Rs[64];

    const int i0 = blockIdx.y * 32;
    const int j0 = blockIdx.x * 64;
    const int tid = threadIdx.x;

    if (tid < DHID) {
        u64 p;
        asm("mov.b64 %0, {%1, %1};" : "=l"(p) : "f"(0.5f * g_s[tid]));
        s2h[tid] = p;
    }
    if (tid < 32) Ps[tid] = g_P[i0 + tid];
    else if (tid < 96) Rs[tid - 32] = g_R[j0 + tid - 32];

    const int ty = tid >> 4;   // 0..7  -> i sub-tile of 4
    const int tx = tid & 15;   // 0..15 -> j sub-tile of 4

    u64 acc2[4][2];   // [i][jpair]
#pragma unroll
    for (int q = 0; q < 4; q++) { acc2[q][0] = 0ull; acc2[q][1] = 0ull; }
    const u64 MASK = 0x7FFFFFFF7FFFFFFFull;

    for (int kc = 0; kc < 2; kc++) {
        __syncthreads();
        // A tile: 64 rows x 8 float4
        for (int e = tid; e < 64 * 8; e += 128) {
            const int kk = e >> 3, vv = e & 7;
            *(float4*)&As[kk][vv * 4] =
                *(const float4*)&g_At[(kc * 64 + kk) * BDIM + i0 + vv * 4];
        }
        // C tile: 64 rows x 16 float4
        for (int e = tid; e < 64 * 16; e += 128) {
            const int kk = e >> 4, vv = e & 15;
            *(float4*)&Cs[kk][vv * 4] =
                *(const float4*)&g_Ct[(kc * 64 + kk) * BDIM + j0 + vv * 4];
        }
        __syncthreads();

#pragma unroll 8
        for (int kk = 0; kk < 64; kk++) {
            const float4 a4 = *(const float4*)&As[kk][ty * 4];
            const ulonglong2 cp = *(const ulonglong2*)&Cs[kk][tx * 4];
            const u64 sk = s2h[kc * 64 + kk];
            u64 av[4];
            asm("mov.b64 %0, {%1, %1};" : "=l"(av[0]) : "f"(a4.x));
            asm("mov.b64 %0, {%1, %1};" : "=l"(av[1]) : "f"(a4.y));
            asm("mov.b64 %0, {%1, %1};" : "=l"(av[2]) : "f"(a4.z));
            asm("mov.b64 %0, {%1, %1};" : "=l"(av[3]) : "f"(a4.w));
            const u64 cj[2] = {cp.x, cp.y};
#pragma unroll
            for (int q = 0; q < 4; q++) {
#pragma unroll
                for (int r = 0; r < 2; r++) {
                    u64 vs;
                    asm("add.rn.f32x2 %0, %1, %2;" : "=l"(vs) : "l"(av[q]), "l"(cj[r]));
                    vs &= MASK;   // |.| on both packed lanes
                    asm("fma.rn.f32x2 %0, %1, %2, %3;"
                        : "=l"(acc2[q][r]) : "l"(vs), "l"(sk), "l"(acc2[q][r]));
                }
            }
        }
    }

    const float t = g_t[0];
    const float r0 = Rs[tx * 4 + 0];
    const float r1 = Rs[tx * 4 + 1];
    const float r2 = Rs[tx * 4 + 2];
    const float r3 = Rs[tx * 4 + 3];
#pragma unroll
    for (int q = 0; q < 4; q++) {
        float v0, v1, v2, v3;
        asm("mov.b64 {%0, %1}, %2;" : "=f"(v0), "=f"(v1) : "l"(acc2[q][0]));
        asm("mov.b64 {%0, %1}, %2;" : "=f"(v2), "=f"(v3) : "l"(acc2[q][1]));
        const float base = t + Ps[ty * 4 + q];
        float4 o;
        o.x = v0 + base + r0;
        o.y = v1 + base + r1;
        o.z = v2 + base + r2;
        o.w = v3 + base + r3;
        *(float4*)&out[(size_t)(i0 + ty * 4 + q) * BDIM + j0 + tx * 4] = o;
    }
}

// ---------------------------------------------------------------------------
extern "C" void kernel_launch(void* const* d_in, const int* in_sizes, int n_in,
                              void* d_out, int out_size)
{
    const float* x     = (const float*)d_in[0];
    const float* W1    = (const float*)d_in[1];
    const float* b1    = (const float*)d_in[2];
    const float* gamma = (const float*)d_in[3];
    const float* beta  = (const float*)d_in[4];
    const float* W2    = (const float*)d_in[5];
    const float* b2    = (const float*)d_in[6];
    float* out = (float*)d_out;

    prep_kernel<<<BDIM / 4, 128>>>(x, W1, b1);
    sortstats_kernel<<<DHID, 256>>>(gamma, beta, W2);
    finalize_pr_kernel<<<17, 128>>>(b2);
    pass2_kernel<<<dim3(16, 32), 128>>>(out);
}